// round 1
// baseline (speedup 1.0000x reference)
#include <cuda_runtime.h>
#include <cstdint>

// Problem constants
#define T_TOK 65536            // B*L = 32*2048 tokens
#define HDIM 256
#define KDIM 1536              // 6*H concat input dim
#define NDIM 1536              // 6 gates * H outputs
#define SEQ_MASK 2047          // L-1

// GEMM tiling
#define BM 128
#define BN 128
#define BK 32
#define KTILES (KDIM / BK)     // 48
#define ASTRIDE 36             // padded row stride (floats) for As[BM][ASTRIDE]
#define BSTRIDE 136            // padded row stride (floats) for Bs[BK][BSTRIDE]
#define SMEM_FLOATS (2*BM*ASTRIDE + 2*BK*BSTRIDE)   // 9216 + 8704 = 17920 floats = 71680 B

// Scratch (device globals: allocation-free rule)
__device__ float g_Wt[(size_t)KDIM * NDIM];            // [k][n], n = g*256+h, tf32-rounded
__device__ float g_gates[(size_t)T_TOK * NDIM];        // [t][n]

__device__ __forceinline__ uint32_t f2tf(float x) {
    uint32_t r;
    asm("cvt.rna.tf32.f32 %0, %1;" : "=r"(r) : "f"(x));
    return r;
}

// ---------------------------------------------------------------------------
// Prep: W_t[k*NDIM + g*256 + h] = tf32(Ws[g][k][h])
// ---------------------------------------------------------------------------
__global__ void prep_w_kernel(const float* __restrict__ Ws) {
    int id = blockIdx.x * blockDim.x + threadIdx.x;
    if (id >= KDIM * NDIM) return;
    int k = id / NDIM;
    int n = id - k * NDIM;
    int g = n >> 8;
    int h = n & 255;
    float v = Ws[((size_t)g * KDIM + k) * HDIM + h];
    g_Wt[id] = __uint_as_float(f2tf(v));
}

// ---------------------------------------------------------------------------
// GEMM: gates[t][n] = sum_k A[t][k] * W_t[k][n]
// A is virtual: chunk c = k/256 selects {h_t, h_t<<1, h_t>>1, x, h_slot, h_intent}
// ---------------------------------------------------------------------------
__device__ __forceinline__ void cp16(uint32_t dst, const void* src, uint32_t sz) {
    asm volatile("cp.async.ca.shared.global [%0], [%1], 16, %2;\n"
                 :: "r"(dst), "l"(src), "r"(sz));
}
__device__ __forceinline__ void cp16f(uint32_t dst, const void* src) {
    asm volatile("cp.async.ca.shared.global [%0], [%1], 16;\n"
                 :: "r"(dst), "l"(src));
}

__global__ __launch_bounds__(256) void gemm_kernel(
    const float* __restrict__ h_t, const float* __restrict__ x,
    const float* __restrict__ h_slot, const float* __restrict__ h_intent)
{
    extern __shared__ float smem[];
    float* As = smem;                       // [2][BM][ASTRIDE]
    float* Bs = smem + 2 * BM * ASTRIDE;    // [2][BK][BSTRIDE]

    const int tid  = threadIdx.x;
    const int warp = tid >> 5;
    const int lane = tid & 31;
    const int wm = warp & 3;     // 4 warps along M
    const int wn = warp >> 2;    // 2 warps along N
    const int gID = lane >> 2;   // 0..7
    const int t4  = lane & 3;    // 0..3
    const int rowbase = blockIdx.y * BM;
    const int colbase = blockIdx.x * BN;

    uint32_t sA = (uint32_t)__cvta_generic_to_shared(As);
    uint32_t sB = (uint32_t)__cvta_generic_to_shared(Bs);

    float acc[2][8][4];
#pragma unroll
    for (int i = 0; i < 2; i++)
#pragma unroll
        for (int j = 0; j < 8; j++)
#pragma unroll
            for (int k = 0; k < 4; k++) acc[i][j][k] = 0.0f;

    auto issue = [&](int kt, int buf) {
        const int chunk = kt >> 3;             // BK=32 divides 256 -> one chunk per k-tile
        const int j0 = (kt & 7) * 32;
        const float* base;
        int shift = 0, mode = 0;               // mode: 0 plain, 1 left, 2 right
        if      (chunk == 0) { base = h_t; }
        else if (chunk == 1) { base = h_t; shift = -1; mode = 1; }
        else if (chunk == 2) { base = h_t; shift =  1; mode = 2; }
        else if (chunk == 3) { base = x; }
        else if (chunk == 4) { base = h_slot; }
        else                 { base = h_intent; }
#pragma unroll
        for (int i = 0; i < 4; i++) {
            int idx = tid + i * 256;
            int r  = idx >> 3;
            int f4 = idx & 7;
            int t  = rowbase + r;
            int l  = t & SEQ_MASK;
            bool valid = (mode == 0) || (mode == 1 ? (l != 0) : (l != SEQ_MASK));
            const float* src = valid ? (base + (size_t)(t + shift) * HDIM + j0 + f4 * 4)
                                     : base;   // clamped; src-size=0 copies nothing
            uint32_t dst = sA + (uint32_t)((buf * BM * ASTRIDE + r * ASTRIDE + f4 * 4) * 4);
            cp16(dst, src, valid ? 16u : 0u);
        }
        const float* wbase = g_Wt + (size_t)(kt * BK) * NDIM + colbase;
#pragma unroll
        for (int i = 0; i < 4; i++) {
            int idx = tid + i * 256;
            int r  = idx >> 5;
            int f4 = idx & 31;
            uint32_t dst = sB + (uint32_t)((buf * BK * BSTRIDE + r * BSTRIDE + f4 * 4) * 4);
            cp16f(dst, wbase + (size_t)r * NDIM + f4 * 4);
        }
        asm volatile("cp.async.commit_group;\n");
    };

    issue(0, 0);

#pragma unroll 1
    for (int kt = 0; kt < KTILES; ++kt) {
        const int buf = kt & 1;
        asm volatile("cp.async.wait_group 0;\n");
        __syncthreads();
        if (kt + 1 < KTILES) issue(kt + 1, buf ^ 1);

        const float* A0 = As + buf * BM * ASTRIDE;
        const float* B0 = Bs + buf * BK * BSTRIDE;

#pragma unroll
        for (int ks = 0; ks < 4; ++ks) {
            uint32_t a[2][4], b[8][2];
            const int k0 = ks * 8 + t4;
#pragma unroll
            for (int mt = 0; mt < 2; mt++) {
                int r = wm * 32 + mt * 16 + gID;
                a[mt][0] = f2tf(A0[r       * ASTRIDE + k0]);
                a[mt][1] = f2tf(A0[(r + 8) * ASTRIDE + k0]);
                a[mt][2] = f2tf(A0[r       * ASTRIDE + k0 + 4]);
                a[mt][3] = f2tf(A0[(r + 8) * ASTRIDE + k0 + 4]);
            }
#pragma unroll
            for (int nt = 0; nt < 8; nt++) {
                int c = wn * 64 + nt * 8 + gID;
                b[nt][0] = __float_as_uint(B0[(ks * 8 + t4)     * BSTRIDE + c]);
                b[nt][1] = __float_as_uint(B0[(ks * 8 + t4 + 4) * BSTRIDE + c]);
            }
#pragma unroll
            for (int mt = 0; mt < 2; mt++)
#pragma unroll
                for (int nt = 0; nt < 8; nt++) {
                    asm volatile(
                        "mma.sync.aligned.m16n8k8.row.col.f32.tf32.tf32.f32 "
                        "{%0,%1,%2,%3}, {%4,%5,%6,%7}, {%8,%9}, {%0,%1,%2,%3};\n"
                        : "+f"(acc[mt][nt][0]), "+f"(acc[mt][nt][1]),
                          "+f"(acc[mt][nt][2]), "+f"(acc[mt][nt][3])
                        : "r"(a[mt][0]), "r"(a[mt][1]), "r"(a[mt][2]), "r"(a[mt][3]),
                          "r"(b[nt][0]), "r"(b[nt][1]));
                }
        }
    }

    // Write gates
#pragma unroll
    for (int mt = 0; mt < 2; mt++) {
#pragma unroll
        for (int nt = 0; nt < 8; nt++) {
            int row = rowbase + wm * 32 + mt * 16 + gID;
            int col = colbase + wn * 64 + nt * 8 + t4 * 2;
            float2 v0 = make_float2(acc[mt][nt][0], acc[mt][nt][1]);
            float2 v1 = make_float2(acc[mt][nt][2], acc[mt][nt][3]);
            *(float2*)(g_gates + (size_t)row       * NDIM + col) = v0;
            *(float2*)(g_gates + (size_t)(row + 8) * NDIM + col) = v1;
        }
    }
}

// ---------------------------------------------------------------------------
// Epilogue: activations + softmax-of-sigmoids + state mix
// ---------------------------------------------------------------------------
__device__ __forceinline__ float sigmoidf(float v) { return 1.0f / (1.0f + expf(-v)); }

__global__ __launch_bounds__(256) void epilogue_kernel(
    const float* __restrict__ c_t, const float* __restrict__ bs,
    float* __restrict__ out)
{
    int gid = blockIdx.x * blockDim.x + threadIdx.x;
    if (gid >= T_TOK * 64) return;
    const int t  = gid >> 6;
    const int hc = (gid & 63) << 2;   // float4 offset within H

    const float* gptr = g_gates + (size_t)t * NDIM + hc;
    float4 gi = *(const float4*)(gptr + 0 * 256);
    float4 go = *(const float4*)(gptr + 1 * 256);
    float4 gf = *(const float4*)(gptr + 2 * 256);
    float4 gl = *(const float4*)(gptr + 3 * 256);
    float4 gr = *(const float4*)(gptr + 4 * 256);
    float4 gu = *(const float4*)(gptr + 5 * 256);

    float4 bi = *(const float4*)(bs + 0 * 256 + hc);
    float4 bo = *(const float4*)(bs + 1 * 256 + hc);
    float4 bf = *(const float4*)(bs + 2 * 256 + hc);
    float4 bl = *(const float4*)(bs + 3 * 256 + hc);
    float4 br = *(const float4*)(bs + 4 * 256 + hc);
    float4 bu = *(const float4*)(bs + 5 * 256 + hc);

    float4 cm = *(const float4*)(c_t + (size_t)t * HDIM + hc);
    const int l = t & SEQ_MASK;
    float4 zero4 = make_float4(0.f, 0.f, 0.f, 0.f);
    float4 cl = (l != 0)        ? *(const float4*)(c_t + (size_t)(t - 1) * HDIM + hc) : zero4;
    float4 cr = (l != SEQ_MASK) ? *(const float4*)(c_t + (size_t)(t + 1) * HDIM + hc) : zero4;

    float GI[4] = {gi.x, gi.y, gi.z, gi.w}, GO[4] = {go.x, go.y, go.z, go.w};
    float GF[4] = {gf.x, gf.y, gf.z, gf.w}, GL[4] = {gl.x, gl.y, gl.z, gl.w};
    float GR[4] = {gr.x, gr.y, gr.z, gr.w}, GU[4] = {gu.x, gu.y, gu.z, gu.w};
    float BI[4] = {bi.x, bi.y, bi.z, bi.w}, BO[4] = {bo.x, bo.y, bo.z, bo.w};
    float BF[4] = {bf.x, bf.y, bf.z, bf.w}, BL[4] = {bl.x, bl.y, bl.z, bl.w};
    float BR[4] = {br.x, br.y, br.z, br.w}, BU[4] = {bu.x, bu.y, bu.z, bu.w};
    float CM[4] = {cm.x, cm.y, cm.z, cm.w}, CL[4] = {cl.x, cl.y, cl.z, cl.w};
    float CR[4] = {cr.x, cr.y, cr.z, cr.w};

    float HN[4], CN[4];
#pragma unroll
    for (int j = 0; j < 4; j++) {
        float I = sigmoidf(GI[j] + BI[j]);
        float O = sigmoidf(GO[j] + BO[j]);
        float F = sigmoidf(GF[j] + BF[j]);
        float Lg = sigmoidf(GL[j] + BL[j]);
        float R = sigmoidf(GR[j] + BR[j]);
        float U = tanhf(GU[j] + BU[j]);
        // softmax over the sigmoid values {I, F, Lg, R}
        float ei = expf(I), ef = expf(F), el = expf(Lg), er = expf(R);
        float inv = 1.0f / (ei + ef + el + er);
        float c = (ef * CM[j] + el * CL[j] + er * CR[j] + ei * U) * inv;
        CN[j] = c;
        HN[j] = O * tanhf(c);
    }

    float4 hn4 = make_float4(HN[0], HN[1], HN[2], HN[3]);
    float4 cn4 = make_float4(CN[0], CN[1], CN[2], CN[3]);
    *(float4*)(out + (size_t)t * HDIM + hc) = hn4;
    *(float4*)(out + (size_t)T_TOK * HDIM + (size_t)t * HDIM + hc) = cn4;
}

// ---------------------------------------------------------------------------
// Launch
// ---------------------------------------------------------------------------
extern "C" void kernel_launch(void* const* d_in, const int* in_sizes, int n_in,
                              void* d_out, int out_size) {
    (void)in_sizes; (void)n_in; (void)out_size;
    const float* h_t      = (const float*)d_in[0];
    const float* x        = (const float*)d_in[1];
    const float* h_slot   = (const float*)d_in[2];
    const float* h_intent = (const float*)d_in[3];
    const float* c_t      = (const float*)d_in[4];
    const float* Ws       = (const float*)d_in[5];
    const float* bs       = (const float*)d_in[6];
    float* out = (float*)d_out;

    cudaFuncSetAttribute(gemm_kernel, cudaFuncAttributeMaxDynamicSharedMemorySize,
                         SMEM_FLOATS * 4);

    prep_w_kernel<<<(KDIM * NDIM + 255) / 256, 256>>>(Ws);
    gemm_kernel<<<dim3(NDIM / BN, T_TOK / BM), 256, SMEM_FLOATS * 4>>>(
        h_t, x, h_slot, h_intent);
    epilogue_kernel<<<(T_TOK * 64) / 256, 256>>>(c_t, bs, out);
}